// round 12
// baseline (speedup 1.0000x reference)
#include <cuda_runtime.h>
#include <cuda_bf16.h>
#include <math.h>
#include <stdint.h>

// B=128, T=64, IN=512, CTRL=512, N=128, MM=128, S=3, R=4, W=1
// 4 independent groups of 32 batches; 32 CTAs per group.

// ---------------- persistent device state ----------------
__device__ float g_part1[16 * 128 * 512];                       // gemm1 warp-split partials
__device__ float g_part2[4 * 128 * 928];                        // gemm2 warp-split partials
__device__ __align__(16) __nv_bfloat16 g_xh[128 * 64 * 512];
__device__ __align__(16) __nv_bfloat16 g_xl[128 * 64 * 512];
__device__ __align__(16) __nv_bfloat16 g_WcT_h[512 * 1024];     // Wc^T [n][k]
__device__ __align__(16) __nv_bfloat16 g_WcT_l[512 * 1024];
__device__ __align__(16) __nv_bfloat16 g_WkT_h[928 * 512];      // Wk^T [n][k], rows>=926 zero
__device__ __align__(16) __nv_bfloat16 g_WkT_l[928 * 512];
__device__ __align__(16) __nv_bfloat16 g_acth[128 * 512];
__device__ __align__(16) __nv_bfloat16 g_actl[128 * 512];
__device__ __align__(16) __nv_bfloat16 g_rvh[128 * 512];
__device__ __align__(16) __nv_bfloat16 g_rvl[128 * 512];
__device__ __align__(128) unsigned g_gbar[4 * 32];              // per-group barrier counters

// ---------------- helpers ----------------
__device__ __forceinline__ uint32_t smem_u32(const void* p) {
    uint32_t a;
    asm("{ .reg .u64 t; cvta.to.shared.u64 t, %1; cvt.u32.u64 %0, t; }" : "=r"(a) : "l"(p));
    return a;
}
__device__ __forceinline__ void ldmatrix_x4(uint32_t* r, uint32_t addr) {
    asm volatile("ldmatrix.sync.aligned.m8n8.x4.shared.b16 {%0,%1,%2,%3}, [%4];"
                 : "=r"(r[0]), "=r"(r[1]), "=r"(r[2]), "=r"(r[3]) : "r"(addr));
}
__device__ __forceinline__ void mma_bf16(float* c, const uint32_t* a, uint32_t b0, uint32_t b1) {
    asm volatile("mma.sync.aligned.m16n8k16.row.col.f32.bf16.bf16.f32 "
                 "{%0,%1,%2,%3}, {%4,%5,%6,%7}, {%8,%9}, {%0,%1,%2,%3};"
                 : "+f"(c[0]), "+f"(c[1]), "+f"(c[2]), "+f"(c[3])
                 : "r"(a[0]), "r"(a[1]), "r"(a[2]), "r"(a[3]), "r"(b0), "r"(b1));
}
static __device__ __forceinline__ void bf16_split(float v, __nv_bfloat16& h, __nv_bfloat16& l) {
    h = __float2bfloat16(v);
    l = __float2bfloat16(v - __bfloat162float(h));
}

// ---------------- prep kernels ----------------
__global__ void prep_x_kernel(const float* __restrict__ x) {
    int i = blockIdx.x * blockDim.x + threadIdx.x;
    int st = gridDim.x * blockDim.x;
    for (int j = i; j < 128 * 64 * 512; j += st) {
        __nv_bfloat16 h, l; bf16_split(x[j], h, l);
        g_xh[j] = h; g_xl[j] = l;
    }
    for (int j = i; j < 128 * 512; j += st) {
        g_rvh[j] = __float2bfloat16(0.0f);
        g_rvl[j] = __float2bfloat16(0.0f);
    }
    if (i < 128) g_gbar[i] = 0u;
}
__global__ void prep_w_kernel(const float* __restrict__ Wc, const float* __restrict__ Wk) {
    int i = blockIdx.x * blockDim.x + threadIdx.x;
    int st = gridDim.x * blockDim.x;
    for (int j = i; j < 512 * 1024; j += st) {
        int n = j >> 10, k = j & 1023;
        __nv_bfloat16 h, l; bf16_split(Wc[k * 512 + n], h, l);
        g_WcT_h[j] = h; g_WcT_l[j] = l;
    }
    for (int j = i; j < 928 * 512; j += st) {
        int n = j >> 9, k = j & 511;
        float v = (n < 926) ? Wk[k * 926 + n] : 0.0f;
        __nv_bfloat16 h, l; bf16_split(v, h, l);
        g_WkT_h[j] = h; g_WkT_l[j] = l;
    }
}

// ---------------- per-group barrier (32 CTAs) ----------------
__device__ __forceinline__ void group_sync(unsigned* bar, unsigned target) {
    __syncthreads();
    if (threadIdx.x == 0) {
        asm volatile("red.release.gpu.global.add.u32 [%0], 1;" :: "l"(bar) : "memory");
        unsigned v;
        do {
            asm volatile("ld.relaxed.gpu.global.b32 %0, [%1];" : "=r"(v) : "l"(bar) : "memory");
        } while (v < target);
        asm volatile("fence.acq_rel.gpu;" ::: "memory");
    }
    __syncthreads();
}

// ---------------- the persistent kernel (512 threads, 128 CTAs) ----------------
__global__ void __launch_bounds__(512) ntm_persistent(
    const float* __restrict__ bc, const float* __restrict__ bk,
    float* __restrict__ dout) {
    extern __shared__ float smem[];
    float* sM   = smem;            // 16512 (Mem)
    float* s_w  = smem + 16512;    // 640
    float* s_cn = smem + 17152;    // 512

    uint32_t base_u32 = smem_u32(smem);
    uint32_t tiles_u32 = (base_u32 + 17664u * 4u + 1023u) & ~1023u;
    char* tS = (char*)smem + (tiles_u32 - base_u32);   // 147456 B scratch
    uint32_t aS = tiles_u32;
    float* scratch = (float*)tS;

    const int tid = threadIdx.x;
    const int wid = tid >> 5, lane = tid & 31;
    const int e = blockIdx.x;
    const int g = e >> 5, q = e & 31;
    const int rb = g * 32;                 // group batch rows
    unsigned* bar = &g_gbar[g * 32];

    // per-CTA state init
    for (int i = tid; i < 128 * 128; i += 512) {
        int n = i >> 7, m = i & 127;
        sM[n * 129 + m] = (n == 64) ? 1.0f : 0.0f;
    }
    for (int i = tid; i < 640; i += 512) s_w[i] = 0.0f;
    __syncthreads();
    {
        int m = tid & 127, qt = tid >> 7;
        float cs = 0.0f;
        int n0 = qt * 32;
#pragma unroll 8
        for (int n = n0; n < n0 + 32; n++) { float v = sM[n * 129 + m]; cs += v * v; }
        s_cn[qt * 128 + m] = cs;
    }

    // tile coordinates
    const int cb1 = (q & 7) * 64;          // GEMM1 coltile
    const int csp = q >> 3;                // GEMM1 K-split (0..3), 256 each
    const int cb2 = q * 32;                // GEMM2 coltile (q<29)
    const bool g2on = (q < 29);

    // per-warp constants
    const int kw = wid & 3, mh = (wid >> 2) & 1, nh = wid >> 3;
    const int l8 = lane & 7, sel = lane >> 3;
    const uint32_t aRowOff = (uint32_t)(mh * 16 + (lane & 15)) * 144u + (uint32_t)(lane >> 4) * 16u;
    const uint32_t bRowOff1 = (uint32_t)(nh * 32 + l8 + ((sel >> 1) * 8)) * 144u + (uint32_t)((sel & 1) * 16);
    const uint32_t bRowOff2 = (uint32_t)(nh * 16 + l8 + ((sel >> 1) * 8)) * 144u + (uint32_t)((sel & 1) * 16);
    const int erow = lane >> 2, ecol = (lane & 3) * 2;

    unsigned nsync = 0;

    for (int t = 0; t < 64; t++) {
        // =========== GEMM1: part1 = [x_t|rv](32 rows, K-slice 256) @ Wc tile ===========
        {
            // stage A (32x256 hi/lo, 4 slabs of 64) : 1024 quads/buffer, 2 iters
#pragma unroll
            for (int it = 0; it < 2; it++) {
                int qd = tid + it * 512;
                int slab = qd >> 8, r = (qd >> 3) & 31, qq = qd & 7;
                size_t src;
                const __nv_bfloat16 *sh, *sl;
                if (csp < 2) {
                    src = ((size_t)(rb + r) * 64 + t) * 512 + csp * 256 + slab * 64 + qq * 8;
                    sh = g_xh; sl = g_xl;
                } else {
                    src = (size_t)(rb + r) * 512 + (csp - 2) * 256 + slab * 64 + qq * 8;
                    sh = g_rvh; sl = g_rvl;
                }
                uint32_t d = slab * 4608 + r * 144 + qq * 16;
                *(uint4*)(tS + d)         = *(const uint4*)(sh + src);
                *(uint4*)(tS + 18432 + d) = *(const uint4*)(sl + src);
            }
            // stage B (64x256 hi/lo, 4 slabs of 64) : 2048 quads/buffer, 4 iters
#pragma unroll
            for (int it = 0; it < 4; it++) {
                int qd = tid + it * 512;
                int slab = qd >> 9, r = (qd >> 3) & 63, qq = qd & 7;
                size_t src = (size_t)(cb1 + r) * 1024 + csp * 256 + slab * 64 + qq * 8;
                uint32_t d = slab * 9216 + r * 144 + qq * 16;
                *(uint4*)(tS + 36864 + d) = *(const uint4*)(g_WcT_h + src);
                *(uint4*)(tS + 73728 + d) = *(const uint4*)(g_WcT_l + src);
            }
            __syncthreads();

            // warp tile m16 x n32 x k64 (slab kw)
            uint32_t Ah[4][4], Al[4][4];
            uint32_t aBase = aS + kw * 4608 + aRowOff;
#pragma unroll
            for (int ks = 0; ks < 4; ks++) {
                ldmatrix_x4(Ah[ks], aBase + ks * 32);
                ldmatrix_x4(Al[ks], aBase + 18432 + ks * 32);
            }
            float acc[4][4] = {};
            uint32_t bBase = aS + 36864 + kw * 9216 + bRowOff1;
#pragma unroll
            for (int ks = 0; ks < 4; ks++) {
#pragma unroll
                for (int nf = 0; nf < 2; nf++) {
                    uint32_t Bh[4], Bl[4];
                    ldmatrix_x4(Bh, bBase + nf * 2304 + ks * 32);
                    ldmatrix_x4(Bl, bBase + 36864 + nf * 2304 + ks * 32);
                    mma_bf16(acc[nf * 2 + 0], Ah[ks], Bh[0], Bh[1]);
                    mma_bf16(acc[nf * 2 + 1], Ah[ks], Bh[2], Bh[3]);
                    mma_bf16(acc[nf * 2 + 0], Al[ks], Bh[0], Bh[1]);
                    mma_bf16(acc[nf * 2 + 1], Al[ks], Bh[2], Bh[3]);
                    mma_bf16(acc[nf * 2 + 0], Ah[ks], Bl[0], Bl[1]);
                    mma_bf16(acc[nf * 2 + 1], Ah[ks], Bl[2], Bl[3]);
                }
            }
            int s1 = csp * 4 + kw;
            int row = rb + mh * 16 + erow;
#pragma unroll
            for (int nf2 = 0; nf2 < 4; nf2++) {
                int col = cb1 + nh * 32 + nf2 * 8 + ecol;
                float* dst = &g_part1[(size_t)s1 * 65536 + (size_t)row * 512 + col];
                *(float2*)dst = make_float2(acc[nf2][0], acc[nf2][1]);
                *(float2*)(dst + 8 * 512) = make_float2(acc[nf2][2], acc[nf2][3]);
            }
        }
        group_sync(bar, ++nsync * 32u);

        // =========== ACT: batch rb+q, 512 cols ===========
        {
            int b = rb + q;
            int j = tid;
            float s = bc[j];
#pragma unroll
            for (int sp = 0; sp < 16; sp++) s += g_part1[(size_t)sp * 65536 + (size_t)b * 512 + j];
            float v = tanhf(s);
            dout[((size_t)b * 64 + t) * 512 + j] = v;
            __nv_bfloat16 h, l; bf16_split(v, h, l);
            g_acth[b * 512 + j] = h;
            g_actl[b * 512 + j] = l;
        }
        group_sync(bar, ++nsync * 32u);

        // =========== GEMM2: instr partials = act(32xK512) @ Wk tile(32 cols) ===========
        if (g2on) {
            // stage A = act (32x512 hi/lo, 8 slabs) and B = WkT (32x512 hi/lo): 2048 quads each, 4 iters
#pragma unroll
            for (int it = 0; it < 4; it++) {
                int qd = tid + it * 512;
                int slab = qd >> 8, r = (qd >> 3) & 31, qq = qd & 7;
                size_t ka = slab * 64 + qq * 8;
                size_t srcA = (size_t)(rb + r) * 512 + ka;
                size_t srcB = (size_t)(cb2 + r) * 512 + ka;
                uint32_t d = slab * 4608 + r * 144 + qq * 16;
                *(uint4*)(tS + d)          = *(const uint4*)(g_acth + srcA);
                *(uint4*)(tS + 36864 + d)  = *(const uint4*)(g_actl + srcA);
                *(uint4*)(tS + 73728 + d)  = *(const uint4*)(g_WkT_h + srcB);
                *(uint4*)(tS + 110592 + d) = *(const uint4*)(g_WkT_l + srcB);
            }
            __syncthreads();

            // warp tile m16 x n16 x k128 (slabs kw*2, kw*2+1)
            float acc[2][4] = {};
            uint32_t aBase = aS + aRowOff;
            uint32_t bBase = aS + 73728 + bRowOff2;
#pragma unroll
            for (int ks = 0; ks < 8; ks++) {
                uint32_t so = (uint32_t)(kw * 2 + (ks >> 2)) * 4608u + (ks & 3) * 32u;
                uint32_t Ah[4], Al[4], Bh[4], Bl[4];
                ldmatrix_x4(Ah, aBase + so);
                ldmatrix_x4(Al, aBase + 36864 + so);
                ldmatrix_x4(Bh, bBase + so);
                ldmatrix_x4(Bl, bBase + 36864 + so);
                mma_bf16(acc[0], Ah, Bh[0], Bh[1]);
                mma_bf16(acc[1], Ah, Bh[2], Bh[3]);
                mma_bf16(acc[0], Al, Bh[0], Bh[1]);
                mma_bf16(acc[1], Al, Bh[2], Bh[3]);
                mma_bf16(acc[0], Ah, Bl[0], Bl[1]);
                mma_bf16(acc[1], Ah, Bl[2], Bl[3]);
            }
            int row = rb + mh * 16 + erow;
#pragma unroll
            for (int nf2 = 0; nf2 < 2; nf2++) {
                int col = cb2 + nh * 16 + nf2 * 8 + ecol;
                float* dst = &g_part2[(size_t)kw * 118784 + (size_t)row * 928 + col];
                *(float2*)dst = make_float2(acc[nf2][0], acc[nf2][1]);
                *(float2*)(dst + 8 * 928) = make_float2(acc[nf2][2], acc[nf2][3]);
            }
        }
        group_sync(bar, ++nsync * 32u);

        // =========== HEADS (batch e = rb+q, SMEM-resident Mem) ===========
        {
            float* s_instr = scratch;           // 928
            float* s_rsn   = scratch + 928;     // 128
            float* s_q     = scratch + 1056;    // 640
            float* s_p2    = scratch + 1696;    // 2560
            float* s_wi    = scratch + 4256;    // 640
            int b = rb + q;

            for (int j = tid; j < 926; j += 512) {
                float s = bk[j];
#pragma unroll
                for (int sp = 0; sp < 4; sp++) s += g_part2[(size_t)sp * 118784 + (size_t)b * 928 + j];
                s_instr[j] = s;
            }
            if (tid < 128)
                s_rsn[tid] = rsqrtf(fmaxf(s_cn[tid] + s_cn[128 + tid] + s_cn[256 + tid] + s_cn[384 + tid], 1e-12f));
            __syncthreads();

            if (wid < 5) {
                int basei = (wid < 4) ? wid * 134 : 536;
                float kv[4];
                float ks = 0.0f;
#pragma unroll
                for (int j = 0; j < 4; j++) { int m = lane * 4 + j; kv[j] = s_instr[basei + m]; ks += kv[j] * kv[j]; }
#pragma unroll
                for (int o = 16; o > 0; o >>= 1) ks += __shfl_xor_sync(0xffffffffu, ks, o);
                float rk = rsqrtf(fmaxf(ks, 1e-12f));
#pragma unroll
                for (int j = 0; j < 4; j++) { int m = lane * 4 + j; s_q[wid * 128 + m] = kv[j] * rk * s_rsn[m]; }
            }
            __syncthreads();

            {
                int n = tid & 127, qt = tid >> 7;
                const float* row = &sM[n * 129];
                int m0 = qt * 32;
                float a0 = 0, a1 = 0, a2 = 0, a3 = 0, a4 = 0;
#pragma unroll 4
                for (int m = m0; m < m0 + 32; m++) {
                    float v = row[m];
                    a0 += v * s_q[m];       a1 += v * s_q[128 + m]; a2 += v * s_q[256 + m];
                    a3 += v * s_q[384 + m]; a4 += v * s_q[512 + m];
                }
                s_p2[0 * 512 + qt * 128 + n] = a0;
                s_p2[1 * 512 + qt * 128 + n] = a1;
                s_p2[2 * 512 + qt * 128 + n] = a2;
                s_p2[3 * 512 + qt * 128 + n] = a3;
                s_p2[4 * 512 + qt * 128 + n] = a4;
            }
            __syncthreads();

            if (wid < 5) {
                int basei = (wid < 4) ? wid * 134 : 536;
                float beta = expf(s_instr[basei + 128]);
                float gg = 1.0f / (1.0f + expf(-s_instr[basei + 129]));
                float a0 = s_instr[basei + 130], a1 = s_instr[basei + 131], a2 = s_instr[basei + 132];
                float mxs = fmaxf(a0, fmaxf(a1, a2));
                float e0 = expf(a0 - mxs), e1 = expf(a1 - mxs), e2 = expf(a2 - mxs);
                float esi = 1.0f / (e0 + e1 + e2);
                float sh0 = e0 * esi, sh1 = e1 * esi, sh2 = e2 * esi;
                float xt = s_instr[basei + 133];
                float tpow = fmaxf(xt, 0.0f) + log1pf(expf(-fabsf(xt))) + 1.0f;

                float vv[4];
                float mx = -3.4e38f;
#pragma unroll
                for (int j = 0; j < 4; j++) {
                    int n = lane * 4 + j;
                    vv[j] = (s_p2[wid * 512 + n] + s_p2[wid * 512 + 128 + n]
                           + s_p2[wid * 512 + 256 + n] + s_p2[wid * 512 + 384 + n]) * beta;
                    mx = fmaxf(mx, vv[j]);
                }
#pragma unroll
                for (int o = 16; o > 0; o >>= 1) mx = fmaxf(mx, __shfl_xor_sync(0xffffffffu, mx, o));
                float ee[4], se = 0.0f;
#pragma unroll
                for (int j = 0; j < 4; j++) { ee[j] = expf(vv[j] - mx); se += ee[j]; }
#pragma unroll
                for (int o = 16; o > 0; o >>= 1) se += __shfl_xor_sync(0xffffffffu, se, o);
                float sei = 1.0f / se;
#pragma unroll
                for (int j = 0; j < 4; j++) {
                    int n = lane * 4 + j;
                    float wold = s_w[wid * 128 + n];
                    s_wi[wid * 128 + n] = ee[j] * sei * gg + wold * (1.0f - gg);
                }
                __syncwarp();
                float pp[4], ps = 0.0f;
#pragma unroll
                for (int j = 0; j < 4; j++) {
                    int n = lane * 4 + j;
                    float ws = sh0 * s_wi[wid * 128 + ((n + 127) & 127)]
                             + sh1 * s_wi[wid * 128 + n]
                             + sh2 * s_wi[wid * 128 + ((n + 1) & 127)];
                    pp[j] = powf(ws, tpow);
                    ps += pp[j];
                }
#pragma unroll
                for (int o = 16; o > 0; o >>= 1) ps += __shfl_xor_sync(0xffffffffu, ps, o);
                float psi = 1.0f / (ps + 1e-12f);
#pragma unroll
                for (int j = 0; j < 4; j++) {
                    int n = lane * 4 + j;
                    s_w[wid * 128 + n] = pp[j] * psi;
                }
            }
            __syncthreads();

            {
                int m = tid & 127, qt = tid >> 7;
                float em = s_instr[670 + m];
                float am = s_instr[798 + m];
                float r0 = 0, r1 = 0, r2 = 0, r3 = 0, cs = 0;
                int n0 = qt * 32;
#pragma unroll 4
                for (int n = n0; n < n0 + 32; n++) {
                    float wwn = s_w[512 + n];
                    float Mv = sM[n * 129 + m];
                    Mv = Mv * (1.0f - wwn * em) + wwn * am;
                    sM[n * 129 + m] = Mv;
                    cs += Mv * Mv;
                    r0 += Mv * s_w[n];       r1 += Mv * s_w[128 + n];
                    r2 += Mv * s_w[256 + n]; r3 += Mv * s_w[384 + n];
                }
                s_cn[qt * 128 + m] = cs;
                s_p2[0 * 512 + qt * 128 + m] = r0;
                s_p2[1 * 512 + qt * 128 + m] = r1;
                s_p2[2 * 512 + qt * 128 + m] = r2;
                s_p2[3 * 512 + qt * 128 + m] = r3;
            }
            __syncthreads();
            if (tid < 128) {
#pragma unroll
                for (int r = 0; r < 4; r++) {
                    float rv = s_p2[r * 512 + tid] + s_p2[r * 512 + 128 + tid]
                             + s_p2[r * 512 + 256 + tid] + s_p2[r * 512 + 384 + tid];
                    __nv_bfloat16 h, l; bf16_split(rv, h, l);
                    g_rvh[b * 512 + r * 128 + tid] = h;
                    g_rvl[b * 512 + r * 128 + tid] = l;
                }
            }
        }
        group_sync(bar, ++nsync * 32u);
    }
}

// ---------------- launch ----------------
extern "C" void kernel_launch(void* const* d_in, const int* in_sizes, int n_in,
                              void* d_out, int out_size) {
    const float *x = nullptr, *Wc = nullptr, *bc = nullptr, *Wk = nullptr, *bk = nullptr;
    for (int i = 0; i < n_in; i++) {
        switch (in_sizes[i]) {
            case 128 * 64 * 512: x  = (const float*)d_in[i]; break;
            case 1024 * 512:     Wc = (const float*)d_in[i]; break;
            case 512:            bc = (const float*)d_in[i]; break;
            case 512 * 926:      Wk = (const float*)d_in[i]; break;
            case 926:            bk = (const float*)d_in[i]; break;
        }
    }

    const int SMEM = 17664 * 4 + 1024 + 147456;  // 219136 B
    cudaFuncSetAttribute(ntm_persistent, cudaFuncAttributeMaxDynamicSharedMemorySize, SMEM);

    prep_x_kernel<<<2048, 256>>>(x);
    prep_w_kernel<<<1024, 256>>>(Wc, Wk);
    ntm_persistent<<<128, 512, SMEM>>>(bc, bk, (float*)d_out);
}

// round 13
// speedup vs baseline: 1.1266x; 1.1266x over previous
#include <cuda_runtime.h>
#include <cuda_bf16.h>
#include <math.h>
#include <stdint.h>

// B=128, T=64, IN=512, CTRL=512, N=128, MM=128, S=3, R=4, W=1
// L=134, LW=390, NOUT=926, K1=1024, K2=512
#define NB 128u

// ---------------- persistent device state ----------------
__device__ float g_part1[16 * 128 * 512];                       // gemm1 partials [split][b][col]
__device__ float g_part2[8 * 128 * 960];                        // gemm2 partials [split][b][col]
__device__ __align__(16) __nv_bfloat16 g_xh[128 * 64 * 512];    // x split-bf16
__device__ __align__(16) __nv_bfloat16 g_xl[128 * 64 * 512];
__device__ __align__(16) __nv_bfloat16 g_WcT_h[512 * 1024];     // Wc^T [n][k]
__device__ __align__(16) __nv_bfloat16 g_WcT_l[512 * 1024];
__device__ __align__(16) __nv_bfloat16 g_WkT_h[960 * 512];      // Wk^T [n][k], rows>=926 zero
__device__ __align__(16) __nv_bfloat16 g_WkT_l[960 * 512];
__device__ __align__(16) __nv_bfloat16 g_acth[128 * 512];       // tanh activations split-bf16
__device__ __align__(16) __nv_bfloat16 g_actl[128 * 512];
__device__ __align__(16) __nv_bfloat16 g_rvh[128 * 512];        // read vectors split-bf16
__device__ __align__(16) __nv_bfloat16 g_rvl[128 * 512];
__device__ unsigned g_barrier;

// ---------------- helpers ----------------
__device__ __forceinline__ uint32_t smem_u32(const void* p) {
    uint32_t a;
    asm("{ .reg .u64 t; cvta.to.shared.u64 t, %1; cvt.u32.u64 %0, t; }" : "=r"(a) : "l"(p));
    return a;
}
__device__ __forceinline__ void ldmatrix_x4(uint32_t& r0, uint32_t& r1, uint32_t& r2, uint32_t& r3, uint32_t addr) {
    asm volatile("ldmatrix.sync.aligned.m8n8.x4.shared.b16 {%0,%1,%2,%3}, [%4];"
                 : "=r"(r0), "=r"(r1), "=r"(r2), "=r"(r3) : "r"(addr));
}
__device__ __forceinline__ void mma_bf16(float* c, const uint32_t* a, uint32_t b0, uint32_t b1) {
    asm volatile("mma.sync.aligned.m16n8k16.row.col.f32.bf16.bf16.f32 "
                 "{%0,%1,%2,%3}, {%4,%5,%6,%7}, {%8,%9}, {%0,%1,%2,%3};"
                 : "+f"(c[0]), "+f"(c[1]), "+f"(c[2]), "+f"(c[3])
                 : "r"(a[0]), "r"(a[1]), "r"(a[2]), "r"(a[3]), "r"(b0), "r"(b1));
}
static __device__ __forceinline__ void bf16_split(float v, __nv_bfloat16& h, __nv_bfloat16& l) {
    h = __float2bfloat16(v);
    l = __float2bfloat16(v - __bfloat162float(h));
}

// ---------------- prep kernels (run each replay, highly parallel) ----------------
__global__ void prep_x_kernel(const float* __restrict__ x) {
    int i = blockIdx.x * blockDim.x + threadIdx.x;
    int st = gridDim.x * blockDim.x;
    for (int j = i; j < 128 * 64 * 512; j += st) {
        __nv_bfloat16 h, l; bf16_split(x[j], h, l);
        g_xh[j] = h; g_xl[j] = l;
    }
    for (int j = i; j < 128 * 512; j += st) {
        g_rvh[j] = __float2bfloat16(0.0f);
        g_rvl[j] = __float2bfloat16(0.0f);
    }
    if (i == 0) g_barrier = 0u;
}
__global__ void prep_w_kernel(const float* __restrict__ Wc, const float* __restrict__ Wk) {
    int i = blockIdx.x * blockDim.x + threadIdx.x;
    int st = gridDim.x * blockDim.x;
    for (int j = i; j < 512 * 1024; j += st) {
        int n = j >> 10, k = j & 1023;
        __nv_bfloat16 h, l; bf16_split(Wc[k * 512 + n], h, l);
        g_WcT_h[j] = h; g_WcT_l[j] = l;
    }
    for (int j = i; j < 960 * 512; j += st) {
        int n = j >> 9, k = j & 511;
        float v = (n < 926) ? Wk[k * 926 + n] : 0.0f;
        __nv_bfloat16 h, l; bf16_split(v, h, l);
        g_WkT_h[j] = h; g_WkT_l[j] = l;
    }
}

// ---------------- counter grid barrier (relaxed poll + exit fence; best measured) ----------------
__device__ __forceinline__ void grid_sync(unsigned target) {
    __syncthreads();
    if (threadIdx.x == 0) {
        unsigned* bar = &g_barrier;
        asm volatile("red.release.gpu.global.add.u32 [%0], 1;" :: "l"(bar) : "memory");
        unsigned v;
        do {
            asm volatile("ld.relaxed.gpu.global.b32 %0, [%1];" : "=r"(v) : "l"(bar) : "memory");
        } while (v < target);
        asm volatile("fence.acq_rel.gpu;" ::: "memory");
    }
    __syncthreads();
}

// ---------------- tile staging (row stride 144 B = 72 bf16; 8 quads of 16B per row) ----------------
__device__ __forceinline__ void stage_A144(const __nv_bfloat16* __restrict__ srcH,
                                           const __nv_bfloat16* __restrict__ srcL,
                                           size_t rstride, char* tAh, char* tAl, int tid) {
#pragma unroll
    for (int it = 0; it < 2; it++) {
        int q = tid + it * 512;            // 0..1023
        int r = q >> 3, qq = q & 7;        // 128 rows x 8 quads
        uint4 vh = *(const uint4*)((const char*)(srcH + (size_t)r * rstride) + qq * 16);
        uint4 vl = *(const uint4*)((const char*)(srcL + (size_t)r * rstride) + qq * 16);
        *(uint4*)(tAh + r * 144 + qq * 16) = vh;
        *(uint4*)(tAl + r * 144 + qq * 16) = vl;
    }
}
__device__ __forceinline__ void stage_B144(const __nv_bfloat16* __restrict__ srcH,
                                           const __nv_bfloat16* __restrict__ srcL,
                                           size_t rstride, char* tBh, char* tBl, int tid) {
    int r = tid >> 3, qq = tid & 7;        // 64 rows x 8 quads = 512 quads
    uint4 vh = *(const uint4*)((const char*)(srcH + (size_t)r * rstride) + qq * 16);
    uint4 vl = *(const uint4*)((const char*)(srcL + (size_t)r * rstride) + qq * 16);
    *(uint4*)(tBh + r * 144 + qq * 16) = vh;
    *(uint4*)(tBl + r * 144 + qq * 16) = vl;
}

// ---------------- HMMA 128x64 tile, K=64, 3 passes (hh, lh, hl) ----------------
// 16 warps: grid 8(M) x 2(N), warp tile 16x32, A fragments register-cached.
__device__ __forceinline__ void gemm_tile_hmma(
    uint32_t aAh, uint32_t aAl, uint32_t aBh, uint32_t aBl,
    float* __restrict__ dst, int ldw, int lane, int wid) {
    const int wm = (wid & 7) * 16;
    const int wn = (wid >> 3) * 32;
    const uint32_t aBase = (uint32_t)(wm + (lane & 15)) * 144u + (uint32_t)((lane >> 4) * 16);
    const int l8 = lane & 7, sel = lane >> 3;
    const uint32_t bBase = (uint32_t)(wn + l8 + ((sel >> 1) * 8)) * 144u + (uint32_t)((sel & 1) * 16);

    uint32_t Ah[4][4], Al[4][4];
#pragma unroll
    for (int ks = 0; ks < 4; ks++) {
        ldmatrix_x4(Ah[ks][0], Ah[ks][1], Ah[ks][2], Ah[ks][3], aAh + aBase + ks * 32);
        ldmatrix_x4(Al[ks][0], Al[ks][1], Al[ks][2], Al[ks][3], aAl + aBase + ks * 32);
    }

    float acc[4][4];
#pragma unroll
    for (int nf2 = 0; nf2 < 4; nf2++)
#pragma unroll
        for (int i = 0; i < 4; i++) acc[nf2][i] = 0.0f;

#pragma unroll
    for (int p = 0; p < 3; p++) {
        uint32_t aB = (p == 2) ? aBl : aBh;
        const uint32_t (*A)[4] = (p == 1) ? Al : Ah;
#pragma unroll
        for (int ks = 0; ks < 4; ks++) {
#pragma unroll
            for (int nf = 0; nf < 2; nf++) {
                uint32_t b0, b1, b2, b3;
                ldmatrix_x4(b0, b1, b2, b3, aB + bBase + nf * (16 * 144) + ks * 32);
                mma_bf16(acc[nf * 2 + 0], A[ks], b0, b1);
                mma_bf16(acc[nf * 2 + 1], A[ks], b2, b3);
            }
        }
    }
    const int row = wm + (lane >> 2);
    const int colb = (lane & 3) * 2;
#pragma unroll
    for (int nf2 = 0; nf2 < 4; nf2++) {
        int col = wn + nf2 * 8 + colb;
        *(float2*)&dst[(size_t)row * ldw + col] = make_float2(acc[nf2][0], acc[nf2][1]);
        *(float2*)&dst[(size_t)(row + 8) * ldw + col] = make_float2(acc[nf2][2], acc[nf2][3]);
    }
}

// ---------------- the persistent kernel (512 threads, 128 CTAs) ----------------
// Mem padded to 132 floats/row: 16B-aligned rows (float4 LDS), stride 33 granules -> conflict-free.
__global__ void __launch_bounds__(512) ntm_persistent(
    const float* __restrict__ bc, const float* __restrict__ bk,
    float* __restrict__ dout) {
    extern __shared__ float smem[];
    float* sM   = smem;            // 128*132 = 16896 floats (Mem, persistent)
    float* s_w  = smem + 16896;    // 640 floats (rw[4], ww[1], persistent)
    float* s_cn = smem + 17536;    // 512 floats (colnorm quarter-partials, persistent)

    uint32_t base_u32 = smem_u32(smem);
    uint32_t tiles_u32 = (base_u32 + 18048u * 4u + 1023u) & ~1023u;
    char* tiles = (char*)smem + (tiles_u32 - base_u32);
    char* tAh = tiles;              uint32_t aAh = tiles_u32;
    char* tAl = tiles + 18432;      uint32_t aAl = tiles_u32 + 18432;
    char* tBh = tiles + 36864;      uint32_t aBh = tiles_u32 + 36864;
    char* tBl = tiles + 46080;      uint32_t aBl = tiles_u32 + 46080;
    float* scratch = (float*)tiles; // heads-phase scratch (aliases tiles)

    const int tid = threadIdx.x;
    const int wid = tid >> 5, lane = tid & 31;
    const int e = blockIdx.x;

    // per-CTA state init
    for (int i = tid; i < 128 * 128; i += 512) {
        int n = i >> 7, m = i & 127;
        sM[n * 132 + m] = (n == 64) ? 1.0f : 0.0f;
    }
    for (int i = tid; i < 640; i += 512) s_w[i] = 0.0f;
    __syncthreads();
    {
        int m = tid & 127, qt = tid >> 7;
        float cs = 0.0f;
        int n0 = qt * 32;
#pragma unroll 8
        for (int n = n0; n < n0 + 32; n++) { float v = sM[n * 132 + m]; cs += v * v; }
        s_cn[qt * 128 + m] = cs;
    }
    __syncthreads();

    // tile coordinates
    const int g1_n0 = (e & 7) * 64;          // 8 coltiles
    const int g1_sp = e >> 3;                // 16 K-splits (K slice 64)
    const int g1_k0 = g1_sp * 64;
    const int g2_n0 = (e % 15) * 64;         // 15 coltiles (960)
    const int g2_sp = e / 15;                // 8 K-splits
    const int g2_k0 = g2_sp * 64;

    unsigned nsync = 0;

    for (int t = 0; t < 64; t++) {
        // =========== GEMM1 (HMMA): part1 = [x_t | rv] @ Wc ===========
        {
            const __nv_bfloat16 *ah, *al;
            size_t rs;
            if (g1_k0 < 512) { ah = g_xh + (size_t)t * 512 + g1_k0; al = g_xl + (size_t)t * 512 + g1_k0; rs = 64 * 512; }
            else             { ah = g_rvh + (g1_k0 - 512);          al = g_rvl + (g1_k0 - 512);          rs = 512; }
            stage_A144(ah, al, rs, tAh, tAl, tid);
            stage_B144(g_WcT_h + (size_t)g1_n0 * 1024 + g1_k0, g_WcT_l + (size_t)g1_n0 * 1024 + g1_k0,
                       1024, tBh, tBl, tid);
            __syncthreads();
            gemm_tile_hmma(aAh, aAl, aBh, aBl,
                           &g_part1[(size_t)(g1_sp * 128) * 512 + g1_n0], 512, lane, wid);
        }
        grid_sync(++nsync * NB);

        // =========== ACT: tanh(sum 16 partials + bc) ===========
        {
            int j = tid;   // 512 threads x 1 col
            float s = bc[j];
#pragma unroll
            for (int sp = 0; sp < 16; sp++) s += g_part1[(size_t)(sp * 128 + e) * 512 + j];
            float v = tanhf(s);
            dout[((size_t)e * 64 + t) * 512 + j] = v;
            __nv_bfloat16 h, l; bf16_split(v, h, l);
            g_acth[e * 512 + j] = h;
            g_actl[e * 512 + j] = l;
        }
        grid_sync(++nsync * NB);

        // =========== GEMM2 (HMMA): part2 = act @ Wk ===========
        if (e < 120) {
            stage_A144(g_acth + g2_k0, g_actl + g2_k0, 512, tAh, tAl, tid);
            stage_B144(g_WkT_h + (size_t)g2_n0 * 512 + g2_k0, g_WkT_l + (size_t)g2_n0 * 512 + g2_k0,
                       512, tBh, tBl, tid);
            __syncthreads();
            gemm_tile_hmma(aAh, aAl, aBh, aBl,
                           &g_part2[(size_t)(g2_sp * 128) * 960 + g2_n0], 960, lane, wid);
        }
        grid_sync(++nsync * NB);

        // =========== HEADS (per-batch, SMEM-resident Mem, vectorized) ===========
        {
            float* s_instr = scratch;           // 928
            float* s_rsn   = scratch + 928;     // 128
            float* s_q     = scratch + 1056;    // 640
            float* s_p2    = scratch + 1696;    // 5*512 = 2560
            float* s_wi    = scratch + 4256;    // 640

            for (int j = tid; j < 926; j += 512) {
                float s = bk[j];
#pragma unroll
                for (int sp = 0; sp < 8; sp++) s += g_part2[(size_t)(sp * 128 + e) * 960 + j];
                s_instr[j] = s;
            }
            if (tid < 128)
                s_rsn[tid] = rsqrtf(fmaxf(s_cn[tid] + s_cn[128 + tid] + s_cn[256 + tid] + s_cn[384 + tid], 1e-12f));
            __syncthreads();

            // key l2-norm + q (warp h = head h)
            if (wid < 5) {
                int basei = (wid < 4) ? wid * 134 : 536;
                float kv[4];
                float ks = 0.0f;
#pragma unroll
                for (int j = 0; j < 4; j++) { int m = lane * 4 + j; kv[j] = s_instr[basei + m]; ks += kv[j] * kv[j]; }
#pragma unroll
                for (int o = 16; o > 0; o >>= 1) ks += __shfl_xor_sync(0xffffffffu, ks, o);
                float rk = rsqrtf(fmaxf(ks, 1e-12f));
#pragma unroll
                for (int j = 0; j < 4; j++) { int m = lane * 4 + j; s_q[wid * 128 + m] = kv[j] * rk * s_rsn[m]; }
            }
            __syncthreads();

            // sim matvec (512 threads: n x quarter), float4 row + float4 broadcast q
            {
                int n = tid & 127, qt = tid >> 7;
                const float* row = &sM[n * 132];
                int m0 = qt * 32;
                float a0 = 0, a1 = 0, a2 = 0, a3 = 0, a4 = 0;
#pragma unroll
                for (int mc = 0; mc < 32; mc += 4) {
                    int m = m0 + mc;
                    float4 rv4 = *(const float4*)&row[m];
                    float4 q0 = *(const float4*)&s_q[m];
                    float4 q1 = *(const float4*)&s_q[128 + m];
                    float4 q2 = *(const float4*)&s_q[256 + m];
                    float4 q3 = *(const float4*)&s_q[384 + m];
                    float4 q4 = *(const float4*)&s_q[512 + m];
                    a0 += rv4.x * q0.x + rv4.y * q0.y + rv4.z * q0.z + rv4.w * q0.w;
                    a1 += rv4.x * q1.x + rv4.y * q1.y + rv4.z * q1.z + rv4.w * q1.w;
                    a2 += rv4.x * q2.x + rv4.y * q2.y + rv4.z * q2.z + rv4.w * q2.w;
                    a3 += rv4.x * q3.x + rv4.y * q3.y + rv4.z * q3.z + rv4.w * q3.w;
                    a4 += rv4.x * q4.x + rv4.y * q4.y + rv4.z * q4.z + rv4.w * q4.w;
                }
                s_p2[0 * 512 + qt * 128 + n] = a0;
                s_p2[1 * 512 + qt * 128 + n] = a1;
                s_p2[2 * 512 + qt * 128 + n] = a2;
                s_p2[3 * 512 + qt * 128 + n] = a3;
                s_p2[4 * 512 + qt * 128 + n] = a4;
            }
            __syncthreads();

            // per-head chain (warp h), shuffle-only reductions
            if (wid < 5) {
                int basei = (wid < 4) ? wid * 134 : 536;
                float beta = expf(s_instr[basei + 128]);
                float gg = 1.0f / (1.0f + expf(-s_instr[basei + 129]));
                float a0 = s_instr[basei + 130], a1 = s_instr[basei + 131], a2 = s_instr[basei + 132];
                float mxs = fmaxf(a0, fmaxf(a1, a2));
                float e0 = expf(a0 - mxs), e1 = expf(a1 - mxs), e2 = expf(a2 - mxs);
                float esi = 1.0f / (e0 + e1 + e2);
                float sh0 = e0 * esi, sh1 = e1 * esi, sh2 = e2 * esi;
                float xt = s_instr[basei + 133];
                float tpow = fmaxf(xt, 0.0f) + log1pf(expf(-fabsf(xt))) + 1.0f;

                float vv[4];
                float mx = -3.4e38f;
#pragma unroll
                for (int j = 0; j < 4; j++) {
                    int n = lane * 4 + j;
                    vv[j] = (s_p2[wid * 512 + n] + s_p2[wid * 512 + 128 + n]
                           + s_p2[wid * 512 + 256 + n] + s_p2[wid * 512 + 384 + n]) * beta;
                    mx = fmaxf(mx, vv[j]);
                }
#pragma unroll
                for (int o = 16; o > 0; o >>= 1) mx = fmaxf(mx, __shfl_xor_sync(0xffffffffu, mx, o));
                float ee[4], se = 0.0f;
#pragma unroll
                for (int j = 0; j < 4; j++) { ee[j] = expf(vv[j] - mx); se += ee[j]; }
#pragma unroll
                for (int o = 16; o > 0; o >>= 1) se += __shfl_xor_sync(0xffffffffu, se, o);
                float sei = 1.0f / se;
#pragma unroll
                for (int j = 0; j < 4; j++) {
                    int n = lane * 4 + j;
                    float wold = s_w[wid * 128 + n];
                    s_wi[wid * 128 + n] = ee[j] * sei * gg + wold * (1.0f - gg);
                }
                __syncwarp();
                float pp[4], ps = 0.0f;
#pragma unroll
                for (int j = 0; j < 4; j++) {
                    int n = lane * 4 + j;
                    float ws = sh0 * s_wi[wid * 128 + ((n + 127) & 127)]
                             + sh1 * s_wi[wid * 128 + n]
                             + sh2 * s_wi[wid * 128 + ((n + 1) & 127)];
                    pp[j] = powf(ws, tpow);
                    ps += pp[j];
                }
#pragma unroll
                for (int o = 16; o > 0; o >>= 1) ps += __shfl_xor_sync(0xffffffffu, ps, o);
                float psi = 1.0f / (ps + 1e-12f);
#pragma unroll
                for (int j = 0; j < 4; j++) {
                    int n = lane * 4 + j;
                    s_w[wid * 128 + n] = pp[j] * psi;
                }
            }
            __syncthreads();

            // erase/add (W=1) + rv partials + fused colnorm; float4 broadcast weights
            {
                int m = tid & 127, qt = tid >> 7;
                float em = s_instr[670 + m];   // 536 + 134 + m
                float am = s_instr[798 + m];   // 536 + 262 + m
                float r0 = 0, r1 = 0, r2 = 0, r3 = 0, cs = 0;
                int n0 = qt * 32;
#pragma unroll
                for (int nc = n0; nc < n0 + 32; nc += 4) {
                    float4 ww4 = *(const float4*)&s_w[512 + nc];
                    float4 w0 = *(const float4*)&s_w[nc];
                    float4 w1 = *(const float4*)&s_w[128 + nc];
                    float4 w2 = *(const float4*)&s_w[256 + nc];
                    float4 w3 = *(const float4*)&s_w[384 + nc];
                    const float* ww = &ww4.x;
                    const float* p0 = &w0.x; const float* p1 = &w1.x;
                    const float* p2 = &w2.x; const float* p3 = &w3.x;
#pragma unroll
                    for (int u = 0; u < 4; u++) {
                        int n = nc + u;
                        float Mv = sM[n * 132 + m];
                        Mv = Mv * (1.0f - ww[u] * em) + ww[u] * am;
                        sM[n * 132 + m] = Mv;
                        cs += Mv * Mv;
                        r0 += Mv * p0[u]; r1 += Mv * p1[u];
                        r2 += Mv * p2[u]; r3 += Mv * p3[u];
                    }
                }
                s_cn[qt * 128 + m] = cs;
                s_p2[0 * 512 + qt * 128 + m] = r0;
                s_p2[1 * 512 + qt * 128 + m] = r1;
                s_p2[2 * 512 + qt * 128 + m] = r2;
                s_p2[3 * 512 + qt * 128 + m] = r3;
            }
            __syncthreads();
            if (tid < 128) {
#pragma unroll
                for (int r = 0; r < 4; r++) {
                    float rv = s_p2[r * 512 + tid] + s_p2[r * 512 + 128 + tid]
                             + s_p2[r * 512 + 256 + tid] + s_p2[r * 512 + 384 + tid];
                    __nv_bfloat16 h, l; bf16_split(rv, h, l);
                    g_rvh[e * 512 + r * 128 + tid] = h;
                    g_rvl[e * 512 + r * 128 + tid] = l;
                }
            }
        }
        grid_sync(++nsync * NB);
    }
}

// ---------------- launch ----------------
extern "C" void kernel_launch(void* const* d_in, const int* in_sizes, int n_in,
                              void* d_out, int out_size) {
    const float *x = nullptr, *Wc = nullptr, *bc = nullptr, *Wk = nullptr, *bk = nullptr;
    for (int i = 0; i < n_in; i++) {
        switch (in_sizes[i]) {
            case 128 * 64 * 512: x  = (const float*)d_in[i]; break;
            case 1024 * 512:     Wc = (const float*)d_in[i]; break;
            case 512:            bc = (const float*)d_in[i]; break;
            case 512 * 926:      Wk = (const float*)d_in[i]; break;
            case 926:            bk = (const float*)d_in[i]; break;
        }
    }

    // smem: 18048 floats (sM@132 + s_w + s_cn) + 1KB align slack + 55296B tiles
    const int SMEM = 18048 * 4 + 1024 + 55296;  // 128512 B
    cudaFuncSetAttribute(ntm_persistent, cudaFuncAttributeMaxDynamicSharedMemorySize, SMEM);

    prep_x_kernel<<<2048, 256>>>(x);
    prep_w_kernel<<<1024, 256>>>(Wc, Wk);
    ntm_persistent<<<128, 512, SMEM>>>(bc, bk, (float*)d_out);
}